// round 13
// baseline (speedup 1.0000x reference)
#include <cuda_runtime.h>

// Problem constants
#define B_TOT  2
#define E_TOT  2048
#define N1_TOT 96
#define K_TOT  32
#define CIN    64
#define CB     32
#define COUT   64
#define WCNT   (160*COUT)     // 10240 floats per W_eq group
#define NEG_SLOPE 0.01f

#define NPB    16             // bond feature pairs (CB/2)
#define EPW    4              // edges per warp
#define EPC    32             // edges per CTA
#define GRID_M 128            // 4096/32, all resident (<148 SMs)

#define CTOP_ROWS 192         // B*N1
#define CMID_ROWS 64          // B*K
#define NPREP     32          // CTAs doing prep dots
#define RPP       8           // rows per prep CTA (24 top CTAs, 8 mid CTAs)

// fma on packed f32x2 (feature pairs)
#define FMA2(acc, v, wgt) \
    asm("fma.rn.f32x2 %0, %1, %2, %0;" : "+l"(acc) : "l"(v), "l"(wgt))

// Cross-CTA intermediates:
//   g_ctop[(b*96+n1)*64 + o] = s1[b,n1,:] . Wbar[0:64, o]
//   g_cmid[(b*32+k )*64 + o] = s2[b,k ,:] . Wbar[64:128, o] + b_eq[o]
// Epoch counter: monotonic across graph replays (each run adds exactly 128);
// every CTA computes the same release target — deterministic, no reset.
__device__ float g_ctop[CTOP_ROWS * COUT];
__device__ float g_cmid[CMID_ROWS * COUT];
__device__ unsigned long long g_cnt;

// ---------------------------------------------------------------------------
// Single fused kernel, 128 CTAs x 256 threads (1 CTA/SM, all resident).
//  1. bonds gather
//  2. Wbot: coalesced averaged load -> raw smem; permute to paired in smem
//  3. CTAs 0..31 only: stage 64-row averaged W panel + s rows, 8 prep dots rows
//  4. bonds FMA loop (pre-barrier: depends only on Wbot+vsh)
//  5. device-wide epoch barrier
//  6. load ctop/cmid rows, combine, activation, attention, atomic scatter
// Thread t owns outputs {t, t+32}.
// ---------------------------------------------------------------------------
__global__ void __launch_bounds__(256, 1) fused_kernel(
    const float* __restrict__ sites1,
    const float* __restrict__ sites2,
    const float* __restrict__ bonds,
    const float* __restrict__ W_eq,
    const float* __restrict__ b_eq,
    const float* __restrict__ W_att,
    const float* __restrict__ b_att,
    const int*   __restrict__ idx1,
    const int*   __restrict__ idx2,
    float* __restrict__ out)
{
    __shared__ float Wavg_sh[64 * COUT];     // prep panel (16384 B, prep CTAs only)
    __shared__ float Wraw_sh[CB * COUT];     // averaged Wbot, raw [f][o] (8192 B)
    __shared__ float Wbot_sh[CB * COUT];     // paired layout (8192 B)
    __shared__ float vsh[EPC * CB];          // bonds (4096 B)
    __shared__ float s_sh[RPP * CIN];        // prep s rows (2048 B)

    const int tid  = threadIdx.x;
    const int lane = tid & 31;
    const int w    = tid >> 5;
    const int c    = blockIdx.x;

    // ---- 1: bonds gather + edge metadata ----
    int ctop_off[EPW], cmid_off[EPW];
    #pragma unroll
    for (int j = 0; j < EPW; j++) {
        const int le = w * EPW + j;
        const int ei = c * EPC + le;
        const int b  = ei >> 11;
        const int e  = ei & (E_TOT - 1);
        const int i1 = idx1[e];
        const int i2 = idx2[e];
        ctop_off[j] = (b * N1_TOT + i1) * COUT;
        cmid_off[j] = (b * K_TOT  + i2) * COUT;
        vsh[le * CB + lane] = bonds[(b * E_TOT + e) * CB + lane];
    }
    const float waT = W_att[lane];
    const float waU = W_att[lane + 32];
    const float ba  = b_att[0];

    // ---- 2a: averaged Wbot, coalesced (rows 128..159 are contiguous) ----
    {
        const float4* g0 = (const float4*)(W_eq + 128 * COUT);
        const float4* g1 = (const float4*)(W_eq + WCNT + 128 * COUT);
        const float4* g2 = (const float4*)(W_eq + 2 * WCNT + 128 * COUT);
        const float4* g3 = (const float4*)(W_eq + 3 * WCNT + 128 * COUT);
        float4* dst = (float4*)Wraw_sh;
        #pragma unroll
        for (int j = 0; j < 2; j++) {
            const int i = tid + j * 256;          // 0..511 float4
            const float4 a = g0[i], b4 = g1[i], cc = g2[i], d = g3[i];
            float4 r;
            r.x = 0.25f * (a.x + b4.x + cc.x + d.x);
            r.y = 0.25f * (a.y + b4.y + cc.y + d.y);
            r.z = 0.25f * (a.z + b4.z + cc.z + d.z);
            r.w = 0.25f * (a.w + b4.w + cc.w + d.w);
            dst[i] = r;
        }
    }

    // ---- 3a: prep CTAs stage their 64-row averaged W panel + s rows ----
    const bool is_prep = (c < NPREP);
    const bool is_top  = (c < 24);
    if (is_prep) {
        const int base4 = (is_top ? 0 : CIN) * (COUT / 4);
        const float4* g0 = (const float4*)W_eq + base4;
        const float4* g1 = (const float4*)(W_eq + WCNT) + base4;
        const float4* g2 = (const float4*)(W_eq + 2 * WCNT) + base4;
        const float4* g3 = (const float4*)(W_eq + 3 * WCNT) + base4;
        float4* dst = (float4*)Wavg_sh;
        #pragma unroll
        for (int j = 0; j < 4; j++) {
            const int i = tid + j * 256;          // 0..1023 float4
            const float4 a = g0[i], b4 = g1[i], cc = g2[i], d = g3[i];
            float4 r;
            r.x = 0.25f * (a.x + b4.x + cc.x + d.x);
            r.y = 0.25f * (a.y + b4.y + cc.y + d.y);
            r.z = 0.25f * (a.z + b4.z + cc.z + d.z);
            r.w = 0.25f * (a.w + b4.w + cc.w + d.w);
            dst[i] = r;
        }
        // s rows: 8 rows x 64 = 512 floats, coalesced
        #pragma unroll
        for (int h = 0; h < 2; h++) {
            const int i   = h * 256 + tid;        // 0..511
            const int row = i >> 6;               // 0..7
            const int o   = i & 63;
            const int R   = is_top ? (RPP * c + row) : (RPP * (c - 24) + row);
            s_sh[i] = is_top ? sites1[R * CIN + o] : sites2[R * CIN + o];
        }
    }
    // zero this CTA's out slice (32 of 4096)
    if (tid < 32) out[c * 32 + tid] = 0.0f;
    __syncthreads();

    // ---- 2b: permute Wbot raw -> paired layout, in smem ----
    // paired[ip*128 + t*4 + sl] = raw[(2ip + (sl&1))*64 + t + 32*(sl>>1)]
    #pragma unroll
    for (int j = 0; j < 8; j++) {
        const int i  = tid + j * 256;            // 0..2047
        const int ip = i >> 7, rr = i & 127, t = rr >> 2, sl = rr & 3;
        Wbot_sh[i] = Wraw_sh[(2 * ip + (sl & 1)) * COUT + t + 32 * (sl >> 1)];
    }

    // ---- 3b: prep dots (8 rows x 64 outs, 2 per thread) ----
    if (is_prep) {
        #pragma unroll
        for (int h = 0; h < 2; h++) {
            const int i   = h * 256 + tid;
            const int row = i >> 6;
            const int o   = i & 63;
            float acc = 0.0f;
            #pragma unroll 16
            for (int f = 0; f < CIN; f++)
                acc += s_sh[row * CIN + f] * Wavg_sh[f * COUT + o];
            if (is_top) {
                g_ctop[(RPP * c + row) * COUT + o] = acc;
            } else {
                g_cmid[(RPP * (c - 24) + row) * COUT + o] = acc + b_eq[o];
            }
        }
    }
    __syncthreads();   // Wbot_sh paired ready for everyone

    // ---- 4: bonds FMA loop (pre-barrier) ----
    const ulonglong2* Wq = (const ulonglong2*)Wbot_sh;
    const float* vb = vsh + (w * EPW) * CB;

    unsigned long long aT[EPW], aU[EPW];
    #pragma unroll
    for (int j = 0; j < EPW; j++) { aT[j] = 0ull; aU[j] = 0ull; }

    #pragma unroll
    for (int ip = 0; ip < NPB; ip++) {
        const ulonglong2 wq = Wq[ip * 32 + lane];
        #pragma unroll
        for (int j = 0; j < EPW; j++) {
            const unsigned long long vp =
                *(const unsigned long long*)(vb + j * CB + 2 * ip);  // broadcast
            FMA2(aT[j], vp, wq.x);
            FMA2(aU[j], vp, wq.y);
        }
    }

    // ---- 5: device-wide epoch barrier ----
    __threadfence();          // release: publish g_ctop/g_cmid/out-zero
    __syncthreads();
    if (tid == 0) {
        const unsigned long long old = atomicAdd(&g_cnt, 1ull);
        const unsigned long long target = ((old >> 7) << 7) + 128ull;
        while (atomicAdd(&g_cnt, 0ull) < target) __nanosleep(64);
    }
    __syncthreads();
    __threadfence();          // acquire

    // ---- 6: combine + epilogue ----
    #pragma unroll
    for (int j = 0; j < EPW; j++) {
        const float ctT = g_ctop[ctop_off[j] + lane];
        const float ctU = g_ctop[ctop_off[j] + lane + 32];
        const float cmT = g_cmid[cmid_off[j] + lane];
        const float cmU = g_cmid[cmid_off[j] + lane + 32];

        float yT = __uint_as_float((unsigned)(aT[j] & 0xffffffffull))
                 + __uint_as_float((unsigned)(aT[j] >> 32)) + ctT + cmT;
        float yU = __uint_as_float((unsigned)(aU[j] & 0xffffffffull))
                 + __uint_as_float((unsigned)(aU[j] >> 32)) + ctU + cmU;
        yT = (yT > 0.0f) ? yT : NEG_SLOPE * yT;
        yU = (yU > 0.0f) ? yU : NEG_SLOPE * yU;

        float p = yT * waT + yU * waU;
        #pragma unroll
        for (int s = 16; s > 0; s >>= 1)
            p += __shfl_xor_sync(0xffffffffu, p, s);
        const float att = 1.0f / (1.0f + __expf(-(p + ba)));

        float* dst = out + cmid_off[j];   // (b*K + i2)*COUT
        atomicAdd(dst + lane,      att * yT);
        atomicAdd(dst + lane + 32, att * yU);
    }
}

// ---------------------------------------------------------------------------
extern "C" void kernel_launch(void* const* d_in, const int* in_sizes, int n_in,
                              void* d_out, int out_size)
{
    const float* sites1 = (const float*)d_in[0];
    const float* sites2 = (const float*)d_in[1];
    const float* bonds  = (const float*)d_in[2];
    const float* W_eq   = (const float*)d_in[3];
    const float* b_eq   = (const float*)d_in[4];
    const float* W_att  = (const float*)d_in[5];
    const float* b_att  = (const float*)d_in[6];
    // d_in[7] = idx2_oh (unused — collapsed analytically)
    const int*   idx1   = (const int*)d_in[8];
    const int*   idx2   = (const int*)d_in[9];
    // d_in[10], d_in[11] = perms1/perms2 (unused — permutations cancel)
    float* out = (float*)d_out;

    // ONE launch: 128 CTAs x 256 threads, internal device-wide barrier.
    fused_kernel<<<GRID_M, 256>>>(sites1, sites2, bonds, W_eq, b_eq,
                                  W_att, b_att, idx1, idx2, out);
}

// round 14
// speedup vs baseline: 1.2113x; 1.2113x over previous
#include <cuda_runtime.h>

// Problem constants
#define B_TOT  2
#define E_TOT  2048
#define N1_TOT 96
#define K_TOT  32
#define CIN    64
#define CB     32
#define COUT   64
#define WCNT   (160*COUT)     // 10240 floats per W_eq group
#define NEG_SLOPE 0.01f

#define NPB    16             // bond feature pairs (CB/2)
#define EPW    4              // edges per warp
#define EPC    32             // edges per CTA
#define GRID_M 128            // 4096/32, all resident (<148 SMs)

#define CTOP_ROWS 192         // B*N1

// fma on packed f32x2 (feature pairs)
#define FMA2(acc, v, wgt) \
    asm("fma.rn.f32x2 %0, %1, %2, %0;" : "+l"(acc) : "l"(v), "l"(wgt))

// Cross-CTA intermediates:
//   g_ctop[(b*96+n1)*64 + o] = s1[b,n1,:] . Wbar[0:64, o]
//   g_cmid[(b*32+k )*64 + o] = s2[b,k ,:] . Wbar[64:128, o] + b_eq[o]
// Epoch counter: monotonic across graph replays (each run adds exactly 128);
// every CTA computes the same release target — deterministic, no reset.
__device__ float g_ctop[CTOP_ROWS * COUT];
__device__ float g_cmid[B_TOT * K_TOT * COUT];
__device__ unsigned long long g_cnt;

// ---------------------------------------------------------------------------
// Single fused kernel, 128 CTAs x 256 threads (1 CTA/SM, all resident).
// Balanced prep: every CTA computes 2 of the 256 ctop/cmid rows.
//  1. bonds gather + edge metadata
//  2. coalesced averaged loads: 64-row W panel, Wbot (raw), s rows
//  3. prep dots (2 rows) -> STG g_ctop/g_cmid   [drains under 5]
//  4. in-smem permute of Wbot to paired layout
//  5. bonds FMA loop (pre-barrier)
//  6. device-wide epoch barrier
//  7. combine + activation + attention + atomic scatter
// Thread t owns outputs {t, t+32}.
// ---------------------------------------------------------------------------
__global__ void __launch_bounds__(256, 1) fused_kernel(
    const float* __restrict__ sites1,
    const float* __restrict__ sites2,
    const float* __restrict__ bonds,
    const float* __restrict__ W_eq,
    const float* __restrict__ b_eq,
    const float* __restrict__ W_att,
    const float* __restrict__ b_att,
    const int*   __restrict__ idx1,
    const int*   __restrict__ idx2,
    float* __restrict__ out)
{
    __shared__ float Wavg_sh[64 * COUT];   // averaged panel for this CTA's 2 rows (16384 B)
    __shared__ float Wraw_sh[CB * COUT];   // averaged Wbot, raw [f][o] (8192 B)
    __shared__ float Wbot_sh[CB * COUT];   // paired layout (8192 B)
    __shared__ float vsh[EPC * CB];        // bonds (4096 B)
    __shared__ float s_sh[2 * CIN];        // 2 s rows (512 B)

    const int tid  = threadIdx.x;
    const int lane = tid & 31;
    const int w    = tid >> 5;
    const int c    = blockIdx.x;

    // ---- 1: bonds gather + edge metadata ----
    int ctop_off[EPW], cmid_off[EPW];
    #pragma unroll
    for (int j = 0; j < EPW; j++) {
        const int le = w * EPW + j;
        const int ei = c * EPC + le;
        const int b  = ei >> 11;
        const int e  = ei & (E_TOT - 1);
        const int i1 = idx1[e];
        const int i2 = idx2[e];
        ctop_off[j] = (b * N1_TOT + i1) * COUT;
        cmid_off[j] = (b * K_TOT  + i2) * COUT;
        vsh[le * CB + lane] = bonds[(b * E_TOT + e) * CB + lane];
    }
    const float waT = W_att[lane];
    const float waU = W_att[lane + 32];
    const float ba  = b_att[0];

    // ---- 2a: stage averaged W panel for this CTA's 2 rows (coalesced) ----
    // c < 96: rows 2c,2c+1 are ctop (W rows [0,64)); else cmid (W rows [64,128)).
    const bool is_top = (c < 96);
    {
        const int base4 = (is_top ? 0 : CIN) * (COUT / 4);
        const float4* g0 = (const float4*)W_eq + base4;
        const float4* g1 = (const float4*)(W_eq + WCNT) + base4;
        const float4* g2 = (const float4*)(W_eq + 2 * WCNT) + base4;
        const float4* g3 = (const float4*)(W_eq + 3 * WCNT) + base4;
        float4* dst = (float4*)Wavg_sh;
        #pragma unroll
        for (int j = 0; j < 4; j++) {
            const int i = tid + j * 256;          // 0..1023 float4
            const float4 a = g0[i], b4 = g1[i], cc = g2[i], d = g3[i];
            float4 r;
            r.x = 0.25f * (a.x + b4.x + cc.x + d.x);
            r.y = 0.25f * (a.y + b4.y + cc.y + d.y);
            r.z = 0.25f * (a.z + b4.z + cc.z + d.z);
            r.w = 0.25f * (a.w + b4.w + cc.w + d.w);
            dst[i] = r;
        }
    }
    // ---- 2b: averaged Wbot, coalesced (rows 128..159 contiguous) ----
    {
        const float4* g0 = (const float4*)(W_eq + 128 * COUT);
        const float4* g1 = (const float4*)(W_eq + WCNT + 128 * COUT);
        const float4* g2 = (const float4*)(W_eq + 2 * WCNT + 128 * COUT);
        const float4* g3 = (const float4*)(W_eq + 3 * WCNT + 128 * COUT);
        float4* dst = (float4*)Wraw_sh;
        #pragma unroll
        for (int j = 0; j < 2; j++) {
            const int i = tid + j * 256;          // 0..511 float4
            const float4 a = g0[i], b4 = g1[i], cc = g2[i], d = g3[i];
            float4 r;
            r.x = 0.25f * (a.x + b4.x + cc.x + d.x);
            r.y = 0.25f * (a.y + b4.y + cc.y + d.y);
            r.z = 0.25f * (a.z + b4.z + cc.z + d.z);
            r.w = 0.25f * (a.w + b4.w + cc.w + d.w);
            dst[i] = r;
        }
    }
    // ---- 2c: this CTA's 2 s rows (coalesced, threads 0..127) ----
    if (tid < 128) {
        const int half = tid >> 6;                // row within pair
        const int o    = tid & 63;
        const int r    = 2 * c + half;            // global row 0..255
        s_sh[half * CIN + o] = is_top ? sites1[r * CIN + o]
                                      : sites2[(r - CTOP_ROWS) * CIN + o];
    }
    // zero this CTA's out slice (32 of 4096)
    if (tid < 32) out[c * 32 + tid] = 0.0f;
    __syncthreads();

    // ---- 3: prep dots (2 rows x 64 outs; threads 0..127), STG early ----
    if (tid < 128) {
        const int half = tid >> 6;
        const int o    = tid & 63;
        const int r    = 2 * c + half;
        float acc = 0.0f;
        #pragma unroll 16
        for (int f = 0; f < CIN; f++)
            acc += s_sh[half * CIN + f] * Wavg_sh[f * COUT + o];
        if (is_top) g_ctop[r * COUT + o] = acc;
        else        g_cmid[(r - CTOP_ROWS) * COUT + o] = acc + b_eq[o];
    }

    // ---- 4: permute Wbot raw -> paired layout, in smem ----
    // paired[ip*128 + t*4 + sl] = raw[(2ip + (sl&1))*64 + t + 32*(sl>>1)]
    #pragma unroll
    for (int j = 0; j < 8; j++) {
        const int i  = tid + j * 256;            // 0..2047
        const int ip = i >> 7, rr = i & 127, t = rr >> 2, sl = rr & 3;
        Wbot_sh[i] = Wraw_sh[(2 * ip + (sl & 1)) * COUT + t + 32 * (sl >> 1)];
    }
    __syncthreads();   // Wbot_sh ready

    // ---- 5: bonds FMA loop (pre-barrier) ----
    const ulonglong2* Wq = (const ulonglong2*)Wbot_sh;
    const float* vb = vsh + (w * EPW) * CB;

    unsigned long long aT[EPW], aU[EPW];
    #pragma unroll
    for (int j = 0; j < EPW; j++) { aT[j] = 0ull; aU[j] = 0ull; }

    #pragma unroll
    for (int ip = 0; ip < NPB; ip++) {
        const ulonglong2 wq = Wq[ip * 32 + lane];
        #pragma unroll
        for (int j = 0; j < EPW; j++) {
            const unsigned long long vp =
                *(const unsigned long long*)(vb + j * CB + 2 * ip);  // broadcast
            FMA2(aT[j], vp, wq.x);
            FMA2(aU[j], vp, wq.y);
        }
    }

    // ---- 6: device-wide epoch barrier ----
    __threadfence();          // release: publish g_ctop/g_cmid/out-zero
    __syncthreads();
    if (tid == 0) {
        const unsigned long long old = atomicAdd(&g_cnt, 1ull);
        const unsigned long long target = ((old >> 7) << 7) + 128ull;
        while (atomicAdd(&g_cnt, 0ull) < target) __nanosleep(64);
    }
    __syncthreads();
    __threadfence();          // acquire

    // ---- 7: combine + epilogue ----
    #pragma unroll
    for (int j = 0; j < EPW; j++) {
        const float ctT = g_ctop[ctop_off[j] + lane];
        const float ctU = g_ctop[ctop_off[j] + lane + 32];
        const float cmT = g_cmid[cmid_off[j] + lane];
        const float cmU = g_cmid[cmid_off[j] + lane + 32];

        float yT = __uint_as_float((unsigned)(aT[j] & 0xffffffffull))
                 + __uint_as_float((unsigned)(aT[j] >> 32)) + ctT + cmT;
        float yU = __uint_as_float((unsigned)(aU[j] & 0xffffffffull))
                 + __uint_as_float((unsigned)(aU[j] >> 32)) + ctU + cmU;
        yT = (yT > 0.0f) ? yT : NEG_SLOPE * yT;
        yU = (yU > 0.0f) ? yU : NEG_SLOPE * yU;

        float p = yT * waT + yU * waU;
        #pragma unroll
        for (int s = 16; s > 0; s >>= 1)
            p += __shfl_xor_sync(0xffffffffu, p, s);
        const float att = 1.0f / (1.0f + __expf(-(p + ba)));

        float* dst = out + cmid_off[j];   // (b*K + i2)*COUT
        atomicAdd(dst + lane,      att * yT);
        atomicAdd(dst + lane + 32, att * yU);
    }
}

// ---------------------------------------------------------------------------
extern "C" void kernel_launch(void* const* d_in, const int* in_sizes, int n_in,
                              void* d_out, int out_size)
{
    const float* sites1 = (const float*)d_in[0];
    const float* sites2 = (const float*)d_in[1];
    const float* bonds  = (const float*)d_in[2];
    const float* W_eq   = (const float*)d_in[3];
    const float* b_eq   = (const float*)d_in[4];
    const float* W_att  = (const float*)d_in[5];
    const float* b_att  = (const float*)d_in[6];
    // d_in[7] = idx2_oh (unused — collapsed analytically)
    const int*   idx1   = (const int*)d_in[8];
    const int*   idx2   = (const int*)d_in[9];
    // d_in[10], d_in[11] = perms1/perms2 (unused — permutations cancel)
    float* out = (float*)d_out;

    // ONE launch: 128 CTAs x 256 threads, internal device-wide barrier.
    fused_kernel<<<GRID_M, 256>>>(sites1, sites2, bonds, W_eq, b_eq,
                                  W_att, b_att, idx1, idx2, out);
}